// round 15
// baseline (speedup 1.0000x reference)
#include <cuda_runtime.h>
#include <cuda_bf16.h>
#include <math.h>
#include <stdint.h>

#define NJ     140
#define NV     13059
#define NB     28
#define BATCH  512
#define NCOLS  (BATCH * 3)       // 1536
#define PK     576               // padded K per segment
#define K2P    (2 * PK)          // 1152 stored K (hi|lo)
#define MP     13248             // padded M (69 * 192)
#define BM     192
#define BN     192               // multiple of 3 -> 64 whole batches per tile
#define BK     64                // K elems per mainloop iter (128 B/row)
#define NIT    27                // 3 segments x 9 iters
#define ASTRIDE 144              // bytes per smem row (128 data + 16 pad)
#define A_SMEM  (BM * ASTRIDE)   // 27648
#define B_SMEM  (BN * ASTRIDE)   // 27648
#define STG     (A_SMEM + B_SMEM)// 55296
#define NSTAGE 3
#define NTHR   384
#define CSTRIDE 195              // floats, C staging row stride (64-row half)
#define MBAR_OFF (NSTAGE * STG)  // 165888
#define GEMM_SMEM_BYTES (MBAR_OFF + 64)

// Static device scratch (zero-initialized; pad regions never written => stay 0)
__device__ float4        g_R4[NJ * BATCH * 3];
__device__ float4        g_H4[NJ * BATCH * 3];
__device__ __nv_bfloat16 g_A16[(size_t)MP * K2P];     // A' [13248 x 1152] = [hi|lo]
__device__ __nv_bfloat16 g_B16[(size_t)NCOLS * K2P];  // B' [1536 x 1152] = [bh|bl]

// ---------------------------------------------------------------------------
// helpers
// ---------------------------------------------------------------------------
__device__ __forceinline__ uint32_t smem_u32(const void* p) {
    uint32_t a;
    asm("{ .reg .u64 t; cvta.to.shared.u64 t, %1; cvt.u32.u64 %0, t; }"
        : "=r"(a) : "l"(p));
    return a;
}
__device__ __forceinline__ uint32_t pack_bf2(float a, float b) {
    __nv_bfloat162 h = __floats2bfloat162_rn(a, b);
    return *reinterpret_cast<uint32_t*>(&h);
}
__device__ __forceinline__ void ldsm4(uint32_t* r, uint32_t addr) {
    asm volatile("ldmatrix.sync.aligned.m8n8.x4.shared.b16 {%0,%1,%2,%3}, [%4];"
                 : "=r"(r[0]), "=r"(r[1]), "=r"(r[2]), "=r"(r[3]) : "r"(addr));
}
__device__ __forceinline__ void mma16816(float* d, const uint32_t* a,
                                         const uint32_t* b) {
    asm volatile(
        "mma.sync.aligned.m16n8k16.row.col.f32.bf16.bf16.f32 "
        "{%0,%1,%2,%3}, {%4,%5,%6,%7}, {%8,%9}, {%0,%1,%2,%3};"
        : "+f"(d[0]), "+f"(d[1]), "+f"(d[2]), "+f"(d[3])
        : "r"(a[0]), "r"(a[1]), "r"(a[2]), "r"(a[3]), "r"(b[0]), "r"(b[1]));
}
#define MBAR_INIT(a, n) \
    asm volatile("mbarrier.init.shared.b64 [%0], %1;" :: "r"(a), "r"(n) : "memory")
#define MBAR_EXPECT(a, tx) \
    asm volatile("mbarrier.arrive.expect_tx.shared.b64 _, [%0], %1;" \
                 :: "r"(a), "r"(tx) : "memory")
#define BULK_LOAD(dst, src, mbar) \
    asm volatile("cp.async.bulk.shared::cta.global.mbarrier::complete_tx::bytes " \
                 "[%0], [%1], 128, [%2];" \
                 :: "r"(dst), "l"(src), "r"(mbar) : "memory")

__device__ __forceinline__ void mbar_wait(uint32_t mbar, uint32_t parity) {
    asm volatile(
        "{\n\t.reg .pred P;\n\t"
        "W%=:\n\t"
        "mbarrier.try_wait.parity.shared.b64 P, [%0], %1, 0x989680;\n\t"
        "@!P bra W%=;\n\t}"
        :: "r"(mbar), "r"(parity) : "memory");
}

// ---------------------------------------------------------------------------
// Kernel 1: rotations + scaled bone offsets. One thread per (b, j).
// q0=(R00,R01,R02,R10) q1=(R11,R12,R20,R21) q2=(R22,o0,o1,o2)
// ---------------------------------------------------------------------------
__global__ void rot_kernel(const float* __restrict__ pose,
                           const float* __restrict__ bone_len,
                           const float* __restrict__ cbl_in,
                           const float* __restrict__ tpj,
                           const int*   __restrict__ parent,
                           const int*   __restrict__ bone_mapper)
{
    int idx = blockIdx.x * blockDim.x + threadIdx.x;
    if (idx >= BATCH * NJ) return;
    int b = idx / NJ;
    int j = idx - b * NJ;

    float ez = pose[b * NJ * 3 + j * 3 + 0];
    float ey = pose[b * NJ * 3 + j * 3 + 1];
    float ex = pose[b * NJ * 3 + j * 3 + 2];
    float cx, sx, cy, sy, cz, sz;
    sincosf(ex, &sx, &cx);
    sincosf(ey, &sy, &cy);
    sincosf(ez, &sz, &cz);
    float R0 = cz * cy;
    float R1 = cz * sy * sx - sz * cx;
    float R2 = cz * sy * cx + sz * sx;
    float R3 = sz * cy;
    float R4 = sz * sy * sx + cz * cx;
    float R5 = sz * sy * cx - cz * sx;
    float R6 = -sy;
    float R7 = cy * sx;
    float R8 = cy * cx;

    float o0, o1, o2;
    if (j == 0) {
        o0 = tpj[0]; o1 = tpj[1]; o2 = tpj[2];
    } else {
        int p = parent[j];
        float f;
        if (j == 1) {
            f = cbl_in[b];
        } else {
            int bm = bone_mapper[j];
            f = (bm >= 0) ? (2.0f / (1.0f + expf(-bone_len[b * NB + bm] * 0.2f)))
                          : 1.0f;
        }
        o0 = (tpj[j * 3 + 0] - tpj[p * 3 + 0]) * f;
        o1 = (tpj[j * 3 + 1] - tpj[p * 3 + 1]) * f;
        o2 = (tpj[j * 3 + 2] - tpj[p * 3 + 2]) * f;
    }

    size_t o = (size_t)(j * BATCH + b) * 3;
    g_R4[o + 0] = make_float4(R0, R1, R2, R3);
    g_R4[o + 1] = make_float4(R4, R5, R6, R7);
    g_R4[o + 2] = make_float4(R8, o0, o1, o2);
}

// ---------------------------------------------------------------------------
// Kernel 2: kinematic chain (round-4 passing version, unchanged).
// ---------------------------------------------------------------------------
#define CHAIN_BPB 7
__global__ __launch_bounds__(32, 1) void chain_kernel(const int* __restrict__ parent)
{
    __shared__ float4 sh[CHAIN_BPB * 3 * NJ];
    __shared__ int    sPar[NJ];

    for (int i = threadIdx.x; i < NJ; i += blockDim.x) sPar[i] = parent[i];
    __syncthreads();

    int local = threadIdx.x;
    if (local >= CHAIN_BPB * 3) return;
    int lb = local / 3;
    int r  = local - lb * 3;
    int b  = blockIdx.x * CHAIN_BPB + lb;
    if (b >= BATCH) return;

    const size_t stride = (size_t)BATCH * 3;
    const float4* Rb = g_R4 + (size_t)b * 3;
    float4* myhist = sh + (size_t)local * NJ;

    float4 q0 = Rb[0], q1 = Rb[1], q2 = Rb[2];
    float4 row;
    if (r == 0)      row = make_float4(q0.x, q0.y, q0.z, q2.y);
    else if (r == 1) row = make_float4(q0.w, q1.x, q1.y, q2.z);
    else             row = make_float4(q1.z, q1.w, q2.x, q2.w);
    myhist[0] = row;
    g_H4[(size_t)0 * stride + b * 3 + r] = row;

    float4 n0 = Rb[stride + 0];
    float4 n1 = Rb[stride + 1];
    float4 n2 = Rb[stride + 2];

    for (int j = 1; j < NJ; j++) {
        q0 = n0; q1 = n1; q2 = n2;
        if (j < NJ - 1) {
            n0 = Rb[(size_t)(j + 1) * stride + 0];
            n1 = Rb[(size_t)(j + 1) * stride + 1];
            n2 = Rb[(size_t)(j + 1) * stride + 2];
        }
        float4 hp = myhist[sPar[j]];
        float nr0 = hp.x * q0.x + hp.y * q0.w + hp.z * q1.z;
        float nr1 = hp.x * q0.y + hp.y * q1.x + hp.z * q1.w;
        float nr2 = hp.x * q0.z + hp.y * q1.y + hp.z * q2.x;
        float nr3 = hp.x * q2.y + hp.y * q2.z + hp.z * q2.w + hp.w;
        float4 nrow = make_float4(nr0, nr1, nr2, nr3);
        myhist[j] = nrow;
        g_H4[(size_t)j * stride + b * 3 + r] = nrow;
    }
}

// ---------------------------------------------------------------------------
// Kernel 3: G_rel fold -> g_B16 (bf16 hi/lo, [bh | bl]) + jout.
// ---------------------------------------------------------------------------
__global__ void bt16_kernel(const float* __restrict__ tpj,
                            const float* __restrict__ trans,
                            const float* __restrict__ scale,
                            float*       __restrict__ jout)
{
    int idx = blockIdx.x * blockDim.x + threadIdx.x;
    if (idx >= BATCH * NJ) return;
    int b = idx & (BATCH - 1);
    int j = idx >> 9;

    size_t base = (size_t)j * BATCH * 3 + b * 3;
    float4 h0 = g_H4[base + 0];
    float4 h1 = g_H4[base + 1];
    float4 h2 = g_H4[base + 2];

    float s   = scale[b];
    float tr0 = trans[b * 3 + 0];
    float tr1 = trans[b * 3 + 1];
    float tr2 = trans[b * 3 + 2];
    float jx = tpj[j * 3 + 0], jy = tpj[j * 3 + 1], jz = tpj[j * 3 + 2];

    jout[b * NJ * 3 + j * 3 + 0] = h0.w * s + tr0;
    jout[b * NJ * 3 + j * 3 + 1] = h1.w * s + tr1;
    jout[b * NJ * 3 + j * 3 + 2] = h2.w * s + tr2;

    float gt0 = h0.w - (h0.x * jx + h0.y * jy + h0.z * jz);
    float gt1 = h1.w - (h1.x * jx + h1.y * jy + h1.z * jz);
    float gt2 = h2.w - (h2.x * jx + h2.y * jy + h2.z * jz);

    #pragma unroll
    for (int m = 0; m < 3; m++) {
        float4 h  = (m == 0) ? h0 : (m == 1) ? h1 : h2;
        float  gt = (m == 0) ? gt0 : (m == 1) ? gt1 : gt2;
        float  tr = (m == 0) ? tr0 : (m == 1) ? tr1 : tr2;
        float v0 = h.x * s, v1 = h.y * s, v2 = h.z * s, v3 = gt * s + tr;

        uint2 hv, lv;
        hv.x = pack_bf2(v0, v1);
        hv.y = pack_bf2(v2, v3);
        __nv_bfloat162* hp0 = reinterpret_cast<__nv_bfloat162*>(&hv.x);
        __nv_bfloat162* hp1 = reinterpret_cast<__nv_bfloat162*>(&hv.y);
        float l0 = v0 - __bfloat162float(hp0->x);
        float l1 = v1 - __bfloat162float(hp0->y);
        float l2 = v2 - __bfloat162float(hp1->x);
        float l3 = v3 - __bfloat162float(hp1->y);
        lv.x = pack_bf2(l0, l1);
        lv.y = pack_bf2(l2, l3);

        size_t rb = (size_t)(3 * b + m) * K2P + 4 * j;
        *(uint2*)(g_B16 + rb)      = hv;   // bh
        *(uint2*)(g_B16 + rb + PK) = lv;   // bl
    }
}

// ---------------------------------------------------------------------------
// Kernel 4: A' = Wv in bf16 hi/lo, [hi | lo].
// ---------------------------------------------------------------------------
__global__ void wv16_kernel(const float* __restrict__ W,
                            const float* __restrict__ vt)
{
    int idx = blockIdx.x * blockDim.x + threadIdx.x;
    if (idx >= NV * 144) return;
    int v  = idx / 144;
    int k4 = idx - v * 144;

    float v0 = 0.f, v1 = 0.f, v2 = 0.f, v3 = 0.f;
    if (k4 < NJ) {
        float w = W[v * NJ + k4];
        v0 = w * vt[v * 3 + 0];
        v1 = w * vt[v * 3 + 1];
        v2 = w * vt[v * 3 + 2];
        v3 = w;
    }
    uint2 hv, lv;
    hv.x = pack_bf2(v0, v1);
    hv.y = pack_bf2(v2, v3);
    __nv_bfloat162* hp0 = reinterpret_cast<__nv_bfloat162*>(&hv.x);
    __nv_bfloat162* hp1 = reinterpret_cast<__nv_bfloat162*>(&hv.y);
    float l0 = v0 - __bfloat162float(hp0->x);
    float l1 = v1 - __bfloat162float(hp0->y);
    float l2 = v2 - __bfloat162float(hp1->x);
    float l3 = v3 - __bfloat162float(hp1->y);
    lv.x = pack_bf2(l0, l1);
    lv.y = pack_bf2(l2, l3);

    size_t base = (size_t)v * K2P + 4 * k4;
    *(uint2*)(g_A16 + base)      = hv;   // hi
    *(uint2*)(g_A16 + base + PK) = lv;   // lo
}

// ---------------------------------------------------------------------------
// Kernel 5: bf16 mma.sync GEMM v4.  D[192 x 192] per CTA, 384 threads.
// 27 iters = 3 segments x 9: seg0 Ah*Bh, seg1 Ah*Bl, seg2 Al*Bh (dedup'd
// storage). cp.async.bulk (128 B/op, 384 ops/iter vs 3072 LDGSTS) with
// per-stage mbarrier completion -- removes the LSU-accept bottleneck.
// Each thread arrives+expects its own 128 B before issuing its own bulk op
// (per-thread ordering => tx-count never goes negative). Stage s at iter it
// waits parity (it/3)&1. Overwrite safety: wait -> __syncthreads -> prefetch.
// ---------------------------------------------------------------------------
__device__ __forceinline__ void load_stage_bulk(int it, uint32_t stg_base,
                                                uint32_t mbar, int tid,
                                                int m0, int n0)
{
    int seg = (it < 9) ? 0 : (it < 18 ? 1 : 2);
    int off = (it - seg * 9) * BK;
    int kA  = off + (seg == 2 ? PK : 0);   // seg2 reads A-lo
    int kB  = off + (seg == 1 ? PK : 0);   // seg1 reads B-lo

    MBAR_EXPECT(mbar, 128u);               // my arrive + my 128 bytes
    if (tid < BM) {
        const __nv_bfloat16* src = g_A16 + (size_t)(m0 + tid) * K2P + kA;
        BULK_LOAD(stg_base + tid * ASTRIDE,
                  (uint64_t)__cvta_generic_to_global(src), mbar);
    } else {
        int row = tid - BM;
        const __nv_bfloat16* src = g_B16 + (size_t)(n0 + row) * K2P + kB;
        BULK_LOAD(stg_base + A_SMEM + row * ASTRIDE,
                  (uint64_t)__cvta_generic_to_global(src), mbar);
    }
}

__global__ __launch_bounds__(NTHR, 1) void skin_gemm_mma(float* __restrict__ out)
{
    extern __shared__ char smem[];
    uint32_t sbase = smem_u32(smem);
    uint32_t mb    = sbase + MBAR_OFF;
    int tid = threadIdx.x;
    int wid = tid >> 5;
    int lid = tid & 31;
    int wm  = wid >> 2;         // 0..2 -> 64 rows each
    int wn  = wid & 3;          // 0..3 -> 48 cols each
    int m0  = blockIdx.x * BM;
    int n0  = blockIdx.y * BN;

    float d[4][6][4];
    #pragma unroll
    for (int i = 0; i < 4; i++)
        #pragma unroll
        for (int j = 0; j < 6; j++)
            #pragma unroll
            for (int q = 0; q < 4; q++) d[i][j][q] = 0.0f;

    if (tid == 0) {
        #pragma unroll
        for (int s = 0; s < NSTAGE; s++) MBAR_INIT(mb + 8 * s, NTHR);
    }
    __syncthreads();   // init visible to all before any arrive/bulk

    load_stage_bulk(0, sbase, mb + 0, tid, m0, n0);
    load_stage_bulk(1, sbase + STG, mb + 8, tid, m0, n0);

    int a_row = wm * 64 + (lid & 15);
    int a_kof = (lid >> 4) * 16;
    int b_row = wn * 48 + (lid & 7) + ((lid >> 4) << 3);
    int b_kof = ((lid >> 3) & 1) * 16;

    for (int it = 0; it < NIT; it++) {
        mbar_wait(mb + 8 * (it % 3), (it / 3) & 1);
        __syncthreads();   // every warp finished reading buffer (it+2)%3

        if (it + 2 < NIT)
            load_stage_bulk(it + 2, sbase + (uint32_t)((it + 2) % 3) * STG,
                            mb + 8 * ((it + 2) % 3), tid, m0, n0);

        uint32_t cur   = sbase + (uint32_t)(it % 3) * STG;
        uint32_t Abase = cur;
        uint32_t Bbase = cur + A_SMEM;

        #pragma unroll
        for (int ks = 0; ks < 4; ks++) {
            uint32_t af[4][4], bf[6][2];
            #pragma unroll
            for (int i = 0; i < 4; i++)
                ldsm4(af[i], Abase + (a_row + i * 16) * ASTRIDE + ks * 32 + a_kof);
            #pragma unroll
            for (int jp = 0; jp < 3; jp++) {
                uint32_t r[4];
                ldsm4(r, Bbase + (b_row + jp * 16) * ASTRIDE + ks * 32 + b_kof);
                bf[2 * jp + 0][0] = r[0]; bf[2 * jp + 0][1] = r[1];
                bf[2 * jp + 1][0] = r[2]; bf[2 * jp + 1][1] = r[3];
            }
            #pragma unroll
            for (int i = 0; i < 4; i++)
                #pragma unroll
                for (int j = 0; j < 6; j++)
                    mma16816(d[i][j], af[i], bf[j]);
        }
    }

    // ---- epilogue: three 64-row groups staged through smem ----
    // No bulk copies are in flight (last prefetch at it=24 completed & was
    // waited at it=26). Csm overlays stage buffers; barrier orders reuse.
    float* Csm = (float*)smem;
    int group = lid >> 2;
    int t4    = lid & 3;
    int bb0   = blockIdx.y * 64;

    __syncthreads();
    #pragma unroll
    for (int h = 0; h < 3; h++) {
        if (wm == h) {
            #pragma unroll
            for (int i = 0; i < 4; i++) {
                int r0 = i * 16 + group;
                #pragma unroll
                for (int j = 0; j < 6; j++) {
                    int c0 = wn * 48 + j * 8 + t4 * 2;
                    Csm[r0 * CSTRIDE + c0]           = d[i][j][0];
                    Csm[r0 * CSTRIDE + c0 + 1]       = d[i][j][1];
                    Csm[(r0 + 8) * CSTRIDE + c0]     = d[i][j][2];
                    Csm[(r0 + 8) * CSTRIDE + c0 + 1] = d[i][j][3];
                }
            }
        }
        __syncthreads();
        for (int e = tid; e < 64 * 192; e += NTHR) {
            int bb  = e / 192;          // local batch 0..63
            int r   = e - bb * 192;
            int vl  = r / 3;
            int mm  = r - vl * 3;
            int v   = m0 + h * 64 + vl;
            if (v < NV)
                out[(size_t)(bb0 + bb) * (NV * 3) + v * 3 + mm] =
                    Csm[vl * CSTRIDE + bb * 3 + mm];
        }
        __syncthreads();
    }
}

// ---------------------------------------------------------------------------
// Launch
// ---------------------------------------------------------------------------
extern "C" void kernel_launch(void* const* d_in, const int* in_sizes, int n_in,
                              void* d_out, int out_size)
{
    const float* pose        = (const float*)d_in[0];
    const float* bone_len    = (const float*)d_in[1];
    const float* cbl         = (const float*)d_in[2];
    const float* trans       = (const float*)d_in[3];
    const float* scale       = (const float*)d_in[4];
    const float* v_template  = (const float*)d_in[5];
    const float* tpj         = (const float*)d_in[6];
    const float* weights     = (const float*)d_in[7];
    const int*   parent      = (const int*)d_in[8];
    const int*   bone_mapper = (const int*)d_in[9];

    float* out  = (float*)d_out;
    float* jout = out + (size_t)BATCH * NV * 3;   // V first, then J_out

    int bj = BATCH * NJ;
    rot_kernel<<<(bj + 255) / 256, 256>>>(pose, bone_len, cbl, tpj,
                                          parent, bone_mapper);

    int nblk = (BATCH + CHAIN_BPB - 1) / CHAIN_BPB;
    chain_kernel<<<nblk, 32>>>(parent);

    bt16_kernel<<<(bj + 255) / 256, 256>>>(tpj, trans, scale, jout);

    int wvt = NV * 144;
    wv16_kernel<<<(wvt + 255) / 256, 256>>>(weights, v_template);

    cudaFuncSetAttribute(skin_gemm_mma,
                         cudaFuncAttributeMaxDynamicSharedMemorySize,
                         GEMM_SMEM_BYTES);
    dim3 grid(MP / BM, NCOLS / BN);   // 69 x 8
    skin_gemm_mma<<<grid, NTHR, GEMM_SMEM_BYTES>>>(out);
}